// round 11
// baseline (speedup 1.0000x reference)
#include <cuda_runtime.h>
#include <cuda_fp16.h>
#include <math.h>

#define NS_N 2048
#define NS_B 16

// Packed log2e-domain data (allocation-free rule: __device__ globals)
//   g_int[j] = { s_int, b_int } : s'=s*log2e, B'=B*log2e on 2^-15 int grid
//   g_res[j] = half2{ s_ls, -b_ls } : residuals scaled by 2^10
__device__ int2    g_int[NS_B * NS_N];
__device__ __half2 g_res[NS_B * NS_N];

typedef unsigned long long u64;
__device__ __forceinline__ u64 pk2(float x, float y) {
    u64 r; asm("mov.b64 %0, {%1,%2};" : "=l"(r) : "f"(x), "f"(y)); return r;
}
__device__ __forceinline__ float2 upk2(u64 v) {
    float2 r; asm("mov.b64 {%0,%1}, %2;" : "=f"(r.x), "=f"(r.y) : "l"(v)); return r;
}
__device__ __forceinline__ u64 add2(u64 a, u64 b) {
    u64 d; asm("add.rn.f32x2 %0, %1, %2;" : "=l"(d) : "l"(a), "l"(b)); return d;
}
__device__ __forceinline__ u64 abs2(u64 a) { return a & 0x7FFFFFFF7FFFFFFFull; }
__device__ __forceinline__ float ex2(float x) {
    float r; asm("ex2.approx.ftz.f32 %0, %1;" : "=f"(r) : "f"(x)); return r;
}

// ---------------------------------------------------------------------------
// Kernel 1: Bsum[b][j] = sum_k |s[b][j] - s[b][k]|
// 512 blocks (64 j's each), 8 threads per j, each summing a 256-k slice with
// stride-8 interleaving (consecutive u64s across lanes -> conflict-free
// broadcast LDS). 4 independent f32x2 accumulators, Neumaier flush every
// 32 packed adds (same error cadence as previous rounds). 8 slice partials
// combined in f64 via SMEM; 64 threads run the f64 epilogue (grid splits).
// grid: (N/64, B), block 512
// ---------------------------------------------------------------------------
__global__ __launch_bounds__(512) void ns_bsum_kernel(const float* __restrict__ scores) {
    __shared__ float s[NS_N];
    __shared__ u64 sneg2[NS_N / 2];
    __shared__ double part[512];
    const int b = blockIdx.y;
    {
        const float4* sp4 = (const float4*)(scores + b * NS_N);
        for (int k = threadIdx.x; k < NS_N / 4; k += 512) {
            float4 v = sp4[k];
            ((float4*)s)[k] = v;
            sneg2[2 * k + 0] = pk2(-v.x, -v.y);
            sneg2[2 * k + 1] = pk2(-v.z, -v.w);
        }
    }
    __syncthreads();

    const int jloc = threadIdx.x >> 3;        // 0..63
    const int slice = threadIdx.x & 7;        // 0..7
    const int j = blockIdx.x * 64 + jloc;
    const float sj = s[j];
    const u64 sj2 = pk2(sj, sj);

    // thread's k-slice: u64 indices slice, slice+8, ..., 128 of them
    float sum = 0.0f, comp = 0.0f;
#pragma unroll
    for (int it = 0; it < 4; ++it) {           // 4 flush groups x 32 packed
        u64 A = 0ull, B = 0ull, C = 0ull, D = 0ull;
        const int base = it * 256 + slice;     // u64 index
#pragma unroll
        for (int u = 0; u < 8; ++u) {
            A = add2(A, abs2(add2(sj2, sneg2[base + u * 32])));
            B = add2(B, abs2(add2(sj2, sneg2[base + u * 32 + 8])));
            C = add2(C, abs2(add2(sj2, sneg2[base + u * 32 + 16])));
            D = add2(D, abs2(add2(sj2, sneg2[base + u * 32 + 24])));
        }
        u64 AB = add2(A, B), CD = add2(C, D);
        float2 a = upk2(AB), c = upk2(CD);
        float f = (a.x + a.y) + (c.x + c.y);
        float t = sum + f;
        comp += (fabsf(sum) >= fabsf(f)) ? ((sum - t) + f) : ((f - t) + sum);
        sum = t;
    }
    part[threadIdx.x] = (double)sum + (double)comp;
    __syncthreads();

    if (threadIdx.x < 64) {
        const int jl = threadIdx.x;
        const double* p = part + jl * 8;
        double d = ((p[0] + p[1]) + (p[2] + p[3])) + ((p[4] + p[5]) + (p[6] + p[7]));

        const double LOG2E = 1.4426950408889634074;
        double Bp = d * LOG2E;
        double sp = (double)s[blockIdx.x * 64 + jl] * LOG2E;
        int s_int = (int)llrint(sp * 32768.0);
        int b_int = (int)llrint(Bp * 32768.0);
        float s_ls = (float)((sp - (double)s_int * (1.0 / 32768.0)) * 1024.0);
        float b_ls = (float)((Bp - (double)b_int * (1.0 / 32768.0)) * 1024.0);

        g_int[b * NS_N + blockIdx.x * 64 + jl] = make_int2(s_int, b_int);
        g_res[b * NS_N + blockIdx.x * 64 + jl] = __floats2half2_rn(s_ls, -b_ls);
    }
}

// ---------------------------------------------------------------------------
// Kernel 2: out[b][i][j] = softmax_j( scale_i * s[b][j] - Bsum[b][j] )
// Block = 8 rows x 2048 cols, 512 threads, one float4 column slice/thread.
// Logit (log2 domain) = h*2^-15 + l; h = c0*s_int - b_int EXACT int32.
// Row recurrence: e_{r+1} = e_r * d_j, d_j = 2^(-2 s'_j); per-row scalar
// shifts cancel in softmax => only row 0 needs max subtraction.
// Clamp at m - 2^23 (=256 in log2): safe for the 7-step recurrence.
// Store pass recomputes e0 (register diet). grid: (N/8, B), block 512.
// ---------------------------------------------------------------------------
__global__ __launch_bounds__(512) void ns_softmax_kernel(float* __restrict__ out) {
    __shared__ float red[128];       // [r*16 + w]
    __shared__ int redi[16];
    __shared__ int finm;
    __shared__ float fins[8];

    const int b = blockIdx.y;
    const int ibase = blockIdx.x * 8;
    const int tid = threadIdx.x;
    const int w = tid >> 5;
    const int lane = tid & 31;

    const int4* gi = (const int4*)(g_int + b * NS_N);
    const int4 p01 = gi[2 * tid];
    const int4 p23 = gi[2 * tid + 1];
    const uint4 rq = ((const uint4*)(g_res + b * NS_N))[tid];
    const float2 q0 = __half22float2(*(const __half2*)&rq.x);
    const float2 q1 = __half22float2(*(const __half2*)&rq.y);
    const float2 q2 = __half22float2(*(const __half2*)&rq.z);
    const float2 q3 = __half22float2(*(const __half2*)&rq.w);

    const int c0 = NS_N - 1 - 2 * ibase;
    const float sc0f = (float)c0;

    int h0[4];
    h0[0] = c0 * p01.x - p01.y;
    h0[1] = c0 * p01.z - p01.w;
    h0[2] = c0 * p23.x - p23.y;
    h0[3] = c0 * p23.z - p23.w;

    float l[4];
    l[0] = fmaf(sc0f, q0.x, q0.y) * (1.0f / 1024.0f);
    l[1] = fmaf(sc0f, q1.x, q1.y) * (1.0f / 1024.0f);
    l[2] = fmaf(sc0f, q2.x, q2.y) * (1.0f / 1024.0f);
    l[3] = fmaf(sc0f, q3.x, q3.y) * (1.0f / 1024.0f);

    float d4[4];
    d4[0] = ex2(fmaf((float)p01.x, -1.0f / 16384.0f, q0.x * (-1.0f / 512.0f)));
    d4[1] = ex2(fmaf((float)p01.z, -1.0f / 16384.0f, q1.x * (-1.0f / 512.0f)));
    d4[2] = ex2(fmaf((float)p23.x, -1.0f / 16384.0f, q2.x * (-1.0f / 512.0f)));
    d4[3] = ex2(fmaf((float)p23.z, -1.0f / 16384.0f, q3.x * (-1.0f / 512.0f)));

    // ---- block max of h0 (HW int reduction) ----
    int mymax = max(max(h0[0], h0[1]), max(h0[2], h0[3]));
    int wm = __reduce_max_sync(0xFFFFFFFFu, mymax);
    if (lane == 0) redi[w] = wm;
    __syncthreads();
    if (w == 0) {
        int v = (lane < 16) ? redi[lane] : (-2147483647 - 1);
        v = __reduce_max_sync(0xFFFFFFFFu, v);
        if (lane == 0) finm = v;
    }
    __syncthreads();
    const int m = finm;
    const int mclamp = m - (1 << 23);

    // ---- row-0 exp arguments, then 8 row sums via recurrence ----
    float arg[4];
#pragma unroll
    for (int k = 0; k < 4; ++k) {
        int hc = max(h0[k], mclamp) - m;               // [-2^23, 0]
        arg[k] = fmaf((float)hc, 1.0f / 32768.0f, l[k]);
    }

    float e[4], sum[8];
#pragma unroll
    for (int k = 0; k < 4; ++k) e[k] = ex2(arg[k]);
    sum[0] = (e[0] + e[1]) + (e[2] + e[3]);
#pragma unroll
    for (int r = 1; r < 8; ++r) {
#pragma unroll
        for (int k = 0; k < 4; ++k) e[k] *= d4[k];
        sum[r] = (e[0] + e[1]) + (e[2] + e[3]);
    }

    // ---- packed-pair warp reductions of the 8 sums ----
    u64 s01 = pk2(sum[0], sum[1]);
    u64 s23 = pk2(sum[2], sum[3]);
    u64 s45 = pk2(sum[4], sum[5]);
    u64 s67 = pk2(sum[6], sum[7]);
#pragma unroll
    for (int o = 16; o > 0; o >>= 1) {
        s01 = add2(s01, __shfl_xor_sync(0xFFFFFFFFu, s01, o));
        s23 = add2(s23, __shfl_xor_sync(0xFFFFFFFFu, s23, o));
        s45 = add2(s45, __shfl_xor_sync(0xFFFFFFFFu, s45, o));
        s67 = add2(s67, __shfl_xor_sync(0xFFFFFFFFu, s67, o));
    }
    if (lane == 0) {
        float2 a = upk2(s01), c = upk2(s23), d = upk2(s45), f = upk2(s67);
        red[0 * 16 + w] = a.x; red[1 * 16 + w] = a.y;
        red[2 * 16 + w] = c.x; red[3 * 16 + w] = c.y;
        red[4 * 16 + w] = d.x; red[5 * 16 + w] = d.y;
        red[6 * 16 + w] = f.x; red[7 * 16 + w] = f.y;
    }
    __syncthreads();
    if (w < 8) {
        float v = (lane < 16) ? red[w * 16 + lane] : 0.0f;
#pragma unroll
        for (int o = 8; o > 0; o >>= 1)
            v += __shfl_xor_sync(0xFFFFFFFFu, v, o);
        if (lane == 0) fins[w] = v;
    }
    __syncthreads();

    // ---- store pass: recompute e0, walk the recurrence again ----
#pragma unroll
    for (int k = 0; k < 4; ++k) e[k] = ex2(arg[k]);

    float4* o4 = (float4*)(out + ((size_t)b * NS_N + (size_t)ibase) * NS_N);
#pragma unroll
    for (int r = 0; r < 8; ++r) {
        const float inv = __frcp_rn(fins[r]);
        __stcs(&o4[r * 512 + tid],
               make_float4(e[0] * inv, e[1] * inv, e[2] * inv, e[3] * inv));
        if (r < 7) {
#pragma unroll
            for (int k = 0; k < 4; ++k) e[k] *= d4[k];
        }
    }
}

extern "C" void kernel_launch(void* const* d_in, const int* in_sizes, int n_in,
                              void* d_out, int out_size) {
    const float* scores = (const float*)d_in[0];
    float* out = (float*)d_out;
    (void)in_sizes; (void)n_in; (void)out_size;

    dim3 g1(NS_N / 64, NS_B);
    ns_bsum_kernel<<<g1, 512>>>(scores);

    dim3 g2(NS_N / 8, NS_B);
    ns_softmax_kernel<<<g2, 512>>>(out);
}

// round 12
// speedup vs baseline: 1.0351x; 1.0351x over previous
#include <cuda_runtime.h>
#include <cuda_fp16.h>
#include <math.h>

#define NS_N 2048
#define NS_B 16

// Packed log2e-domain data (allocation-free rule: __device__ globals)
//   g_int[j] = { s_int, b_int } : s'=s*log2e, B'=B*log2e on 2^-15 int grid
//   g_res[j] = half2{ s_ls, -b_ls } : residuals scaled by 2^10
__device__ int2    g_int[NS_B * NS_N];
__device__ __half2 g_res[NS_B * NS_N];

typedef unsigned long long u64;
__device__ __forceinline__ u64 pk2(float x, float y) {
    u64 r; asm("mov.b64 %0, {%1,%2};" : "=l"(r) : "f"(x), "f"(y)); return r;
}
__device__ __forceinline__ float2 upk2(u64 v) {
    float2 r; asm("mov.b64 {%0,%1}, %2;" : "=f"(r.x), "=f"(r.y) : "l"(v)); return r;
}
__device__ __forceinline__ u64 add2(u64 a, u64 b) {
    u64 d; asm("add.rn.f32x2 %0, %1, %2;" : "=l"(d) : "l"(a), "l"(b)); return d;
}
__device__ __forceinline__ u64 abs2(u64 a) { return a & 0x7FFFFFFF7FFFFFFFull; }
__device__ __forceinline__ float ex2(float x) {
    float r; asm("ex2.approx.ftz.f32 %0, %1;" : "=f"(r) : "f"(x)); return r;
}

// ---------------------------------------------------------------------------
// Kernel 1 (R9 config): Bsum[b][j] = sum_k |s[b][j] - s[b][k]|
// SPLIT-K x4: four threads per j (block 1024 = 256 j x 4 quarters), packed
// f32x2 with 4 indep accumulators + Neumaier flushes; quarters combined in
// double via SMEM. Epilogue: int-grid (2^-15) + half-residual (x2^10).
// Triggers programmatic launch completion for the dependent softmax kernel.
// grid: (N/256, B), block 1024
// ---------------------------------------------------------------------------
__global__ __launch_bounds__(1024) void ns_bsum_kernel(const float* __restrict__ scores) {
    __shared__ float s[NS_N];
    __shared__ u64 sneg2[NS_N / 2];
    __shared__ double part[1024];
    const int b = blockIdx.y;
    {
        const float4* sp4 = (const float4*)(scores + b * NS_N);
        for (int k = threadIdx.x; k < NS_N / 4; k += 1024) {
            float4 v = sp4[k];
            ((float4*)s)[k] = v;
            sneg2[2 * k + 0] = pk2(-v.x, -v.y);
            sneg2[2 * k + 1] = pk2(-v.z, -v.w);
        }
    }
    __syncthreads();

    const int jl = threadIdx.x & 255;
    const int quart = threadIdx.x >> 8;
    const int j = blockIdx.x * 256 + jl;
    const float sj = s[j];
    const u64 sj2 = pk2(sj, sj);
    const int kbase = quart * 256;

    float sum = 0.0f, comp = 0.0f;
#pragma unroll 2
    for (int it = 0; it < 8; ++it) {
        u64 A = 0ull, B = 0ull, C = 0ull, D = 0ull;
        const int base = kbase + it * 32;
#pragma unroll
        for (int u = 0; u < 8; ++u) {
            A = add2(A, abs2(add2(sj2, sneg2[base + u])));
            B = add2(B, abs2(add2(sj2, sneg2[base + 8 + u])));
            C = add2(C, abs2(add2(sj2, sneg2[base + 16 + u])));
            D = add2(D, abs2(add2(sj2, sneg2[base + 24 + u])));
        }
        u64 AB = add2(A, B), CD = add2(C, D);
        float2 a = upk2(AB), c = upk2(CD);
        float f = (a.x + a.y) + (c.x + c.y);
        float t = sum + f;
        comp += (fabsf(sum) >= fabsf(f)) ? ((sum - t) + f) : ((f - t) + sum);
        sum = t;
    }
    part[threadIdx.x] = (double)sum + (double)comp;
    __syncthreads();

    if (quart == 0) {
        double d = (part[jl] + part[jl + 256]) + (part[jl + 512] + part[jl + 768]);

        const double LOG2E = 1.4426950408889634074;
        double Bp = d * LOG2E;
        double sp = (double)sj * LOG2E;
        int s_int = (int)llrint(sp * 32768.0);
        int b_int = (int)llrint(Bp * 32768.0);
        float s_ls = (float)((sp - (double)s_int * (1.0 / 32768.0)) * 1024.0);
        float b_ls = (float)((Bp - (double)b_int * (1.0 / 32768.0)) * 1024.0);

        g_int[b * NS_N + j] = make_int2(s_int, b_int);
        g_res[b * NS_N + j] = __floats2half2_rn(s_ls, -b_ls);
    }

#if __CUDA_ARCH__ >= 900
    cudaTriggerProgrammaticLaunchCompletion();
#endif
}

// ---------------------------------------------------------------------------
// Kernel 2 (R9 config + PDL): out[b][i][j] = softmax_j(scale_i*s_j - Bsum_j)
// Block = 8 rows x 2048 cols, 512 threads, one float4 column slice/thread.
// Launched with programmatic stream serialization: CTAs ramp up while
// ns_bsum_kernel still runs; cudaGridDependencySynchronize() gates the reads.
// Logit (log2 domain) = h*2^-15 + l; h = c0*s_int - b_int EXACT int32.
// Row recurrence: e_{r+1} = e_r * d_j, d_j = 2^(-2 s'_j). Clamp m - 2^23.
// grid: (N/8, B), block 512.
// ---------------------------------------------------------------------------
__global__ __launch_bounds__(512) void ns_softmax_kernel(float* __restrict__ out) {
    __shared__ float red[128];
    __shared__ int redi[16];
    __shared__ int finm;
    __shared__ float fins[8];

    const int b = blockIdx.y;
    const int ibase = blockIdx.x * 8;
    const int tid = threadIdx.x;
    const int w = tid >> 5;
    const int lane = tid & 31;

#if __CUDA_ARCH__ >= 900
    cudaGridDependencySynchronize();
#endif

    const int4* gi = (const int4*)(g_int + b * NS_N);
    const int4 p01 = gi[2 * tid];
    const int4 p23 = gi[2 * tid + 1];
    const uint4 rq = ((const uint4*)(g_res + b * NS_N))[tid];
    const float2 q0 = __half22float2(*(const __half2*)&rq.x);
    const float2 q1 = __half22float2(*(const __half2*)&rq.y);
    const float2 q2 = __half22float2(*(const __half2*)&rq.z);
    const float2 q3 = __half22float2(*(const __half2*)&rq.w);

    const int c0 = NS_N - 1 - 2 * ibase;
    const float sc0f = (float)c0;

    int h0[4];
    h0[0] = c0 * p01.x - p01.y;
    h0[1] = c0 * p01.z - p01.w;
    h0[2] = c0 * p23.x - p23.y;
    h0[3] = c0 * p23.z - p23.w;

    float l[4];
    l[0] = fmaf(sc0f, q0.x, q0.y) * (1.0f / 1024.0f);
    l[1] = fmaf(sc0f, q1.x, q1.y) * (1.0f / 1024.0f);
    l[2] = fmaf(sc0f, q2.x, q2.y) * (1.0f / 1024.0f);
    l[3] = fmaf(sc0f, q3.x, q3.y) * (1.0f / 1024.0f);

    float d4[4];
    d4[0] = ex2(fmaf((float)p01.x, -1.0f / 16384.0f, q0.x * (-1.0f / 512.0f)));
    d4[1] = ex2(fmaf((float)p01.z, -1.0f / 16384.0f, q1.x * (-1.0f / 512.0f)));
    d4[2] = ex2(fmaf((float)p23.x, -1.0f / 16384.0f, q2.x * (-1.0f / 512.0f)));
    d4[3] = ex2(fmaf((float)p23.z, -1.0f / 16384.0f, q3.x * (-1.0f / 512.0f)));

    // ---- block max of h0 (HW int reduction) ----
    int mymax = max(max(h0[0], h0[1]), max(h0[2], h0[3]));
    int wm = __reduce_max_sync(0xFFFFFFFFu, mymax);
    if (lane == 0) redi[w] = wm;
    __syncthreads();
    if (w == 0) {
        int v = (lane < 16) ? redi[lane] : (-2147483647 - 1);
        v = __reduce_max_sync(0xFFFFFFFFu, v);
        if (lane == 0) finm = v;
    }
    __syncthreads();
    const int m = finm;
    const int mclamp = m - (1 << 23);

    // ---- row-0 exp arguments, then 8 row sums via recurrence ----
    float arg[4];
#pragma unroll
    for (int k = 0; k < 4; ++k) {
        int hc = max(h0[k], mclamp) - m;
        arg[k] = fmaf((float)hc, 1.0f / 32768.0f, l[k]);
    }

    float e[4], sum[8];
#pragma unroll
    for (int k = 0; k < 4; ++k) e[k] = ex2(arg[k]);
    sum[0] = (e[0] + e[1]) + (e[2] + e[3]);
#pragma unroll
    for (int r = 1; r < 8; ++r) {
#pragma unroll
        for (int k = 0; k < 4; ++k) e[k] *= d4[k];
        sum[r] = (e[0] + e[1]) + (e[2] + e[3]);
    }

    // ---- packed-pair warp reductions of the 8 sums ----
    u64 s01 = pk2(sum[0], sum[1]);
    u64 s23 = pk2(sum[2], sum[3]);
    u64 s45 = pk2(sum[4], sum[5]);
    u64 s67 = pk2(sum[6], sum[7]);
#pragma unroll
    for (int o = 16; o > 0; o >>= 1) {
        s01 = add2(s01, __shfl_xor_sync(0xFFFFFFFFu, s01, o));
        s23 = add2(s23, __shfl_xor_sync(0xFFFFFFFFu, s23, o));
        s45 = add2(s45, __shfl_xor_sync(0xFFFFFFFFu, s45, o));
        s67 = add2(s67, __shfl_xor_sync(0xFFFFFFFFu, s67, o));
    }
    if (lane == 0) {
        float2 a = upk2(s01), c = upk2(s23), d = upk2(s45), f = upk2(s67);
        red[0 * 16 + w] = a.x; red[1 * 16 + w] = a.y;
        red[2 * 16 + w] = c.x; red[3 * 16 + w] = c.y;
        red[4 * 16 + w] = d.x; red[5 * 16 + w] = d.y;
        red[6 * 16 + w] = f.x; red[7 * 16 + w] = f.y;
    }
    __syncthreads();
    if (w < 8) {
        float v = (lane < 16) ? red[w * 16 + lane] : 0.0f;
#pragma unroll
        for (int o = 8; o > 0; o >>= 1)
            v += __shfl_xor_sync(0xFFFFFFFFu, v, o);
        if (lane == 0) fins[w] = v;
    }
    __syncthreads();

    // ---- store pass: recompute e0, walk the recurrence again ----
#pragma unroll
    for (int k = 0; k < 4; ++k) e[k] = ex2(arg[k]);

    float4* o4 = (float4*)(out + ((size_t)b * NS_N + (size_t)ibase) * NS_N);
#pragma unroll
    for (int r = 0; r < 8; ++r) {
        const float inv = __frcp_rn(fins[r]);
        __stcs(&o4[r * 512 + tid],
               make_float4(e[0] * inv, e[1] * inv, e[2] * inv, e[3] * inv));
        if (r < 7) {
#pragma unroll
            for (int k = 0; k < 4; ++k) e[k] *= d4[k];
        }
    }
}

extern "C" void kernel_launch(void* const* d_in, const int* in_sizes, int n_in,
                              void* d_out, int out_size) {
    const float* scores = (const float*)d_in[0];
    float* out = (float*)d_out;
    (void)in_sizes; (void)n_in; (void)out_size;

    dim3 g1(NS_N / 256, NS_B);
    ns_bsum_kernel<<<g1, 1024>>>(scores);

    // Dependent launch with programmatic stream serialization: softmax CTAs
    // ramp while bsum finishes; cudaGridDependencySynchronize() gates reads.
    cudaLaunchConfig_t cfg = {};
    cfg.gridDim = dim3(NS_N / 8, NS_B);
    cfg.blockDim = dim3(512);
    cfg.dynamicSmemBytes = 0;
    cfg.stream = 0;
    cudaLaunchAttribute attrs[1];
    attrs[0].id = cudaLaunchAttributeProgrammaticStreamSerialization;
    attrs[0].val.programmaticStreamSerializationAllowed = 1;
    cfg.attrs = attrs;
    cfg.numAttrs = 1;
    cudaLaunchKernelEx(&cfg, ns_softmax_kernel, out);
}